// round 7
// baseline (speedup 1.0000x reference)
#include <cuda_runtime.h>
#include <cuda_fp16.h>
#include <cstdint>
#include <cstddef>

#define L_SEQ 256
#define BSZ   16
#define VOC   32000
#define HID   512
#define NCTA  128
#define LOGN  ((size_t)L_SEQ * BSZ * VOC)

// ---------------- device scratch (allocation-free) ----------------
__device__ __half   g_wd[(size_t)VOC * HID];            // W_dec fp16   (32.8 MB)
__device__ __half   g_hs[(size_t)L_SEQ * BSZ * HID];    // hidden states fp16 (4 MB)
__device__ float    g_hbuf[2][BSZ * HID];               // double-buffered h (fp32)
__device__ unsigned g_cnt[L_SEQ];                       // grid-barrier counters

// ---------------- prep: convert W_dec to fp16, zero barrier counters ----------------
__global__ void prep_kernel(const float* __restrict__ Wd) {
    size_t n = (size_t)VOC * HID;
    size_t stride = (size_t)gridDim.x * blockDim.x;
    for (size_t i = (size_t)blockIdx.x * blockDim.x + threadIdx.x; i < n; i += stride)
        g_wd[i] = __float2half_rn(Wd[i]);
    if (blockIdx.x == 0 && threadIdx.x < L_SEQ)
        g_cnt[threadIdx.x] = 0u;
}

// ---------------- LSTM recurrence: persistent, weight-stationary ----------------
// 128 CTAs x 256 threads. CTA c owns hidden units [4c, 4c+4).
// Warp w: p = w&1 -> hidden pair j0 = 4c + 2p; bg = w>>1 -> batches [4bg, 4bg+4).
// Each warp computes 8 gate-rows (4 gates x 2 hidden) x 4 batches.
// Lane holds W_hh[row][k] for k = lane + 32*i (i<16), 8 rows -> 128 regs.
__global__ void __launch_bounds__(256, 1) lstm_kernel(
    const int*   __restrict__ tokens,
    const float* __restrict__ W_ih,
    const float* __restrict__ W_hh,
    const float* __restrict__ b_ih,
    const float* __restrict__ b_hh,
    float*       __restrict__ out_tail)   // hL then cL, each BSZ*HID
{
    __shared__ float sh[BSZ * HID];   // 32 KB

    const int tid = threadIdx.x;
    const int w   = tid >> 5;
    const int l   = tid & 31;
    const int cta = blockIdx.x;
    const int p   = w & 1;
    const int bg  = w >> 1;
    const int j0  = cta * 4 + p * 2;
    const int b0  = bg * 4;

    // load W_hh rows into registers (coalesced)
    float wreg[8][16];
#pragma unroll
    for (int r = 0; r < 8; r++) {
        int grow = (r >> 1) * HID + j0 + (r & 1);   // gate g = r>>1, unit jj = r&1
        const float* wp = W_hh + (size_t)grow * HID + l;
#pragma unroll
        for (int i = 0; i < 16; i++) wreg[r][i] = wp[i * 32];
    }

    // embedding/bias lane assignment: lane loads (row r_e = l&7, batch b_e = l>>3)
    const int r_e    = l & 7;
    const int b_e    = l >> 3;
    const int grow_e = (r_e >> 1) * HID + j0 + (r_e & 1);
    const float biasv = b_ih[grow_e] + b_hh[grow_e];

    // gate lanes 0..7: jj = l&1, bb = (l>>1)&3
    const int jj_g = l & 1;
    const int bb_g = (l >> 1) & 3;
    float cstate = 0.f;

    for (int s = 0; s < L_SEQ; s++) {
        // ---- issue embedding gather early (DRAM latency hidden by the dot) ----
        int tok = tokens[s * BSZ + b0 + b_e];
        float embb = W_ih[(size_t)grow_e * VOC + tok] + biasv;

        float acc[32];
#pragma unroll
        for (int z = 0; z < 32; z++) acc[z] = 0.f;

        if (s > 0) {
            // stage full h (prev buffer) into smem, coalesced float4
            const float4* src4 = (const float4*)g_hbuf[(s - 1) & 1];
            float4* dst4 = (float4*)sh;
#pragma unroll
            for (int i = 0; i < 8; i++) dst4[tid + i * 256] = src4[tid + i * 256];
            __syncthreads();

            // matvec: acc[r*4+b] = sum_k W[row_r][k] * h[b0+b][k]
#pragma unroll 4
            for (int i = 0; i < 16; i++) {
#pragma unroll
                for (int b = 0; b < 4; b++) {
                    float hv = sh[(b0 + b) * HID + l + i * 32];
#pragma unroll
                    for (int r = 0; r < 8; r++) acc[r * 4 + b] += wreg[r][i] * hv;
                }
            }
            // butterfly reduce across lanes (every lane ends with all 32 sums)
#pragma unroll
            for (int off = 16; off > 0; off >>= 1) {
#pragma unroll
                for (int z = 0; z < 32; z++)
                    acc[z] += __shfl_xor_sync(0xffffffffu, acc[z], off);
            }
        }

        // gather emb+bias for this lane's (jj,bb) via shuffles; gates i,f,g,o
        float gate[4];
#pragma unroll
        for (int g = 0; g < 4; g++) {
            int src = bb_g * 8 + g * 2 + jj_g;
            float eb = __shfl_sync(0xffffffffu, embb, src);
            gate[g] = eb + acc[(g * 2 + jj_g) * 4 + bb_g];
        }

        if (l < 8) {
            float ii = 1.f / (1.f + __expf(-gate[0]));
            float ff = 1.f / (1.f + __expf(-gate[1]));
            float gg = tanhf(gate[2]);
            float oo = 1.f / (1.f + __expf(-gate[3]));
            cstate = ff * cstate + ii * gg;
            float h = oo * tanhf(cstate);

            int b = b0 + bb_g, j = j0 + jj_g;
            g_hbuf[s & 1][b * HID + j] = h;
            g_hs[((size_t)s * BSZ + b) * HID + j] = __float2half_rn(h);
            if (s == L_SEQ - 1) {
                out_tail[b * HID + j] = h;                   // hL
                out_tail[BSZ * HID + b * HID + j] = cstate;  // cL
            }
        }

        // ---- grid barrier for step s ----
        __syncthreads();            // T0 observes all CTA writes (block scope)
        if (tid == 0) {
            __threadfence();        // publish observed writes at gpu scope
            atomicAdd(&g_cnt[s], 1u);
            unsigned v;
            do {
                asm volatile("ld.acquire.gpu.u32 %0, [%1];" : "=r"(v) : "l"(g_cnt + s));
            } while (v < NCTA);
        }
        __syncthreads();            // propagate acquire block-wide
    }
}

// ---------------- decoder GEMM: C[4096,32000] = A[4096,512] * B[32000,512]^T ----------------
// fp16 inputs from L2, fp32 accum via mma.sync.m16n8k16. CTA tile 128x128,
// warp tile 64x32 (warps 2x4), fragments loaded directly from global (L1/L2 hit).
__device__ __forceinline__ void mma16816(float* d, const uint32_t* a, const uint32_t* b) {
    asm volatile(
        "mma.sync.aligned.m16n8k16.row.col.f32.f16.f16.f32 "
        "{%0,%1,%2,%3}, {%4,%5,%6,%7}, {%8,%9}, {%0,%1,%2,%3};\n"
        : "+f"(d[0]), "+f"(d[1]), "+f"(d[2]), "+f"(d[3])
        : "r"(a[0]), "r"(a[1]), "r"(a[2]), "r"(a[3]), "r"(b[0]), "r"(b[1]));
}

__global__ void __launch_bounds__(256) gemm_kernel(
    const float* __restrict__ b_dec,
    float*       __restrict__ C)
{
    const int wid  = threadIdx.x >> 5;
    const int l    = threadIdx.x & 31;
    const int wm   = wid >> 2;            // 0..1
    const int wn   = wid & 3;             // 0..3
    const int gid  = l >> 2;              // 0..7
    const int tid4 = l & 3;               // 0..3

    const int mbase = blockIdx.y * 128 + wm * 64;
    const int nbase = blockIdx.x * 128 + wn * 32;

    const __half* A = g_hs;
    const __half* B = g_wd;

    // per-lane base offsets (in halfs)
    size_t aoff[4], boff[4];
#pragma unroll
    for (int fm = 0; fm < 4; fm++)
        aoff[fm] = ((size_t)(mbase + fm * 16 + gid)) * HID + tid4 * 2;
#pragma unroll
    for (int fn = 0; fn < 4; fn++)
        boff[fn] = ((size_t)(nbase + fn * 8 + gid)) * HID + tid4 * 2;

    float acc[4][4][4];
#pragma unroll
    for (int fm = 0; fm < 4; fm++)
#pragma unroll
        for (int fn = 0; fn < 4; fn++)
#pragma unroll
            for (int z = 0; z < 4; z++) acc[fm][fn][z] = 0.f;

#pragma unroll 2
    for (int kk = 0; kk < HID; kk += 16) {
        uint32_t a[4][4], b[4][2];
#pragma unroll
        for (int fm = 0; fm < 4; fm++) {
            const __half* ptr = A + aoff[fm] + kk;
            a[fm][0] = *(const uint32_t*)(ptr);
            a[fm][1] = *(const uint32_t*)(ptr + 8 * HID);
            a[fm][2] = *(const uint32_t*)(ptr + 8);
            a[fm][3] = *(const uint32_t*)(ptr + 8 * HID + 8);
        }
#pragma unroll
        for (int fn = 0; fn < 4; fn++) {
            const __half* ptr = B + boff[fn] + kk;
            b[fn][0] = *(const uint32_t*)(ptr);
            b[fn][1] = *(const uint32_t*)(ptr + 8);
        }
#pragma unroll
        for (int fm = 0; fm < 4; fm++)
#pragma unroll
            for (int fn = 0; fn < 4; fn++)
                mma16816(acc[fm][fn], a[fm], b[fn]);
    }

    // epilogue: d0,d1 -> (row, col..col+1); d2,d3 -> (row+8, col..col+1)
#pragma unroll
    for (int fn = 0; fn < 4; fn++) {
        int col = nbase + fn * 8 + tid4 * 2;
        float2 bb2 = *(const float2*)(b_dec + col);
#pragma unroll
        for (int fm = 0; fm < 4; fm++) {
            int row = mbase + fm * 16 + gid;
            float2 v0 = make_float2(acc[fm][fn][0] + bb2.x, acc[fm][fn][1] + bb2.y);
            float2 v1 = make_float2(acc[fm][fn][2] + bb2.x, acc[fm][fn][3] + bb2.y);
            *(float2*)(C + (size_t)row * VOC + col)       = v0;
            *(float2*)(C + (size_t)(row + 8) * VOC + col) = v1;
        }
    }
}

// ---------------- launcher ----------------
extern "C" void kernel_launch(void* const* d_in, const int* in_sizes, int n_in,
                              void* d_out, int out_size) {
    const int*   tokens = (const int*)  d_in[0];
    const float* W_ih   = (const float*)d_in[1];
    const float* W_hh   = (const float*)d_in[2];
    const float* b_ih   = (const float*)d_in[3];
    const float* b_hh   = (const float*)d_in[4];
    const float* W_dec  = (const float*)d_in[5];
    const float* b_dec  = (const float*)d_in[6];
    float* out = (float*)d_out;

    prep_kernel<<<2048, 256>>>(W_dec);
    lstm_kernel<<<NCTA, 256>>>(tokens, W_ih, W_hh, b_ih, b_hh, out + LOGN);
    dim3 g(VOC / 128, (L_SEQ * BSZ) / 128);
    gemm_kernel<<<g, 256>>>(b_dec, out);
}

// round 8
// speedup vs baseline: 1.1782x; 1.1782x over previous
#include <cuda_runtime.h>
#include <cuda_fp16.h>
#include <cstdint>
#include <cstddef>

#define L_SEQ 256
#define BSZ   16
#define VOC   32000
#define HID   512
#define NCTA  128
#define LOGN  ((size_t)L_SEQ * BSZ * VOC)

// ---------------- device scratch (allocation-free) ----------------
__device__ __half   g_wd[(size_t)VOC * HID];            // W_dec fp16   (32.8 MB)
__device__ __half   g_hs[(size_t)L_SEQ * BSZ * HID];    // hidden states fp16 (4 MB)
__device__ float    g_hbuf[2][BSZ * HID];               // double-buffered h (fp32)
__device__ unsigned g_cnt[L_SEQ];                       // grid-barrier counters

// ---------------- prep: convert W_dec to fp16, zero barrier counters ----------------
__global__ void prep_kernel(const float* __restrict__ Wd) {
    size_t n = (size_t)VOC * HID;
    size_t stride = (size_t)gridDim.x * blockDim.x;
    for (size_t i = (size_t)blockIdx.x * blockDim.x + threadIdx.x; i < n; i += stride)
        g_wd[i] = __float2half_rn(Wd[i]);
    if (blockIdx.x == 0 && threadIdx.x < L_SEQ)
        g_cnt[threadIdx.x] = 0u;
}

// ---------------- LSTM recurrence: persistent, weight-stationary ----------------
// 128 CTAs x 256 threads. CTA c owns hidden units [4c, 4c+4).
// Warp w: p = w&1 -> hidden pair j0 = 4c + 2p; bg = w>>1 -> batches [4bg, 4bg+4).
// Warp computes 32 output scalars: o = r*4 + bb, r = g*2+jj (g gate, jj hidden
// unit within pair), bb batch within group. Lane l holds W_hh[row(r=l>>2)][k]
// for k = l + 32*i; a combining butterfly lands the fully-reduced sum for
// output o = l on lane l (ALL array indices compile-time).
__global__ void __launch_bounds__(256, 1) lstm_kernel(
    const int*   __restrict__ tokens,
    const float* __restrict__ W_ih,
    const float* __restrict__ W_hh,
    const float* __restrict__ b_ih,
    const float* __restrict__ b_hh,
    float*       __restrict__ out_tail)   // hL then cL, each BSZ*HID
{
    __shared__ float sh[BSZ * HID];   // 32 KB staged h

    const int tid = threadIdx.x;
    const int w   = tid >> 5;
    const int l   = tid & 31;
    const int cta = blockIdx.x;
    const int p   = w & 1;
    const int bg  = w >> 1;
    const int j0  = cta * 4 + p * 2;
    const int b0  = bg * 4;

    // ---- weight-stationary W_hh rows (fully static register array) ----
    // row(r) = gate(r>>1)*HID + j0 + (r&1);  lane l holds k = l + 32*i
    float wreg[8][16];
#pragma unroll
    for (int r = 0; r < 8; r++) {
        const int grow = (r >> 1) * HID + j0 + (r & 1);
        const float* wp = W_hh + (size_t)grow * HID + l;
#pragma unroll
        for (int i = 0; i < 16; i++) wreg[r][i] = wp[i * 32];
    }

    // ---- per-lane output identity: o = l -> r = l>>2, bb = l&3 ----
    const int r_o   = l >> 2;               // 0..7
    const int bb_o  = l & 3;                // 0..3
    const int row_o = (r_o >> 1) * HID + j0 + (r_o & 1);   // row in [0,4H)
    const float biasv = b_ih[row_o] + b_hh[row_o];

    // activation lanes l<8: jj = l>>2, bb = l&3
    const int jj_a = l >> 2;
    const int bb_a = l & 3;
    float cstate = 0.f;

    for (int s = 0; s < L_SEQ; s++) {
        // ---- issue embedding gather early (DRAM latency hidden by matvec) ----
        const int tok = tokens[s * BSZ + b0 + bb_o];
        const float embb = W_ih[(size_t)row_o * VOC + tok] + biasv;

        float acc[32];
#pragma unroll
        for (int z = 0; z < 32; z++) acc[z] = 0.f;

        if (s > 0) {
            // stage full h (prev buffer) into smem, coalesced float4
            const float4* src4 = (const float4*)g_hbuf[(s - 1) & 1];
            float4* dst4 = (float4*)sh;
#pragma unroll
            for (int i = 0; i < 8; i++) dst4[tid + i * 256] = src4[tid + i * 256];
            __syncthreads();

            // matvec: acc[r*4+b] += W[row_r][k] * h[b0+b][k], k = l + 32*i
            // FULLY unrolled: every wreg/acc index is compile-time.
#pragma unroll
            for (int i = 0; i < 16; i++) {
#pragma unroll
                for (int b = 0; b < 4; b++) {
                    const float hv = sh[(b0 + b) * HID + l + i * 32];
#pragma unroll
                    for (int r = 0; r < 8; r++) acc[r * 4 + b] += wreg[r][i] * hv;
                }
            }

            // combining butterfly: after round D, acc[z] (z<D) holds the
            // partial for output o = z + (l & ~(2D-1) bits processed); after
            // all rounds lane l holds the full sum for output o = l.
#define RED_ROUND(D)                                                          \
            {                                                                 \
                _Pragma("unroll")                                             \
                for (int z = 0; z < (D); z++) {                               \
                    const float vk = (l & (D)) ? acc[z + (D)] : acc[z];       \
                    const float vg = (l & (D)) ? acc[z] : acc[z + (D)];       \
                    acc[z] = vk + __shfl_xor_sync(0xffffffffu, vg, (D));      \
                }                                                             \
            }
            RED_ROUND(16) RED_ROUND(8) RED_ROUND(4) RED_ROUND(2) RED_ROUND(1)
#undef RED_ROUND
        }

        // lane l now owns pre-activation (minus emb) for output o = l
        const float total = acc[0] + embb;

        // gather the 4 gates for (jj = l>>2, bb = l&3): sources g*8 + (l&7)
        float gate0 = __shfl_sync(0xffffffffu, total, (l & 7));
        float gate1 = __shfl_sync(0xffffffffu, total, (l & 7) + 8);
        float gate2 = __shfl_sync(0xffffffffu, total, (l & 7) + 16);
        float gate3 = __shfl_sync(0xffffffffu, total, (l & 7) + 24);

        if (l < 8) {
            const float ii = 1.f / (1.f + __expf(-gate0));
            const float ff = 1.f / (1.f + __expf(-gate1));
            const float gg = tanhf(gate2);
            const float oo = 1.f / (1.f + __expf(-gate3));
            cstate = ff * cstate + ii * gg;
            const float h = oo * tanhf(cstate);

            const int b = b0 + bb_a, j = j0 + jj_a;
            g_hbuf[s & 1][b * HID + j] = h;
            g_hs[((size_t)s * BSZ + b) * HID + j] = __float2half_rn(h);
            if (s == L_SEQ - 1) {
                out_tail[b * HID + j] = h;                   // hL
                out_tail[BSZ * HID + b * HID + j] = cstate;  // cL
            }
        }

        // ---- grid barrier for step s ----
        __syncthreads();            // CTA-wide: all writes issued
        if (tid == 0) {
            __threadfence();        // publish at gpu scope
            asm volatile("red.release.gpu.global.add.u32 [%0], %1;"
                         :: "l"(g_cnt + s), "r"(1u) : "memory");
            unsigned v;
            do {
                asm volatile("ld.acquire.gpu.u32 %0, [%1];" : "=r"(v) : "l"(g_cnt + s));
            } while (v < NCTA);
        }
        __syncthreads();            // propagate acquire block-wide
    }
}

// ---------------- decoder GEMM: C[4096,32000] = A[4096,512] * B[32000,512]^T ----------------
// fp16 inputs from L2, fp32 accum via mma.sync.m16n8k16. CTA tile 128x128,
// warp tile 64x32 (warps 2x4), fragments loaded directly from global (L1/L2 hit).
__device__ __forceinline__ void mma16816(float* d, const uint32_t* a, const uint32_t* b) {
    asm volatile(
        "mma.sync.aligned.m16n8k16.row.col.f32.f16.f16.f32 "
        "{%0,%1,%2,%3}, {%4,%5,%6,%7}, {%8,%9}, {%0,%1,%2,%3};\n"
        : "+f"(d[0]), "+f"(d[1]), "+f"(d[2]), "+f"(d[3])
        : "r"(a[0]), "r"(a[1]), "r"(a[2]), "r"(a[3]), "r"(b[0]), "r"(b[1]));
}

__global__ void __launch_bounds__(256) gemm_kernel(
    const float* __restrict__ b_dec,
    float*       __restrict__ C)
{
    const int wid  = threadIdx.x >> 5;
    const int l    = threadIdx.x & 31;
    const int wm   = wid >> 2;            // 0..1
    const int wn   = wid & 3;             // 0..3
    const int gid  = l >> 2;              // 0..7
    const int tid4 = l & 3;               // 0..3

    const int mbase = blockIdx.y * 128 + wm * 64;
    const int nbase = blockIdx.x * 128 + wn * 32;

    const __half* A = g_hs;
    const __half* B = g_wd;

    size_t aoff[4], boff[4];
#pragma unroll
    for (int fm = 0; fm < 4; fm++)
        aoff[fm] = ((size_t)(mbase + fm * 16 + gid)) * HID + tid4 * 2;
#pragma unroll
    for (int fn = 0; fn < 4; fn++)
        boff[fn] = ((size_t)(nbase + fn * 8 + gid)) * HID + tid4 * 2;

    float acc[4][4][4];
#pragma unroll
    for (int fm = 0; fm < 4; fm++)
#pragma unroll
        for (int fn = 0; fn < 4; fn++)
#pragma unroll
            for (int z = 0; z < 4; z++) acc[fm][fn][z] = 0.f;

#pragma unroll 2
    for (int kk = 0; kk < HID; kk += 16) {
        uint32_t a[4][4], b[4][2];
#pragma unroll
        for (int fm = 0; fm < 4; fm++) {
            const __half* ptr = A + aoff[fm] + kk;
            a[fm][0] = *(const uint32_t*)(ptr);
            a[fm][1] = *(const uint32_t*)(ptr + 8 * HID);
            a[fm][2] = *(const uint32_t*)(ptr + 8);
            a[fm][3] = *(const uint32_t*)(ptr + 8 * HID + 8);
        }
#pragma unroll
        for (int fn = 0; fn < 4; fn++) {
            const __half* ptr = B + boff[fn] + kk;
            b[fn][0] = *(const uint32_t*)(ptr);
            b[fn][1] = *(const uint32_t*)(ptr + 8);
        }
#pragma unroll
        for (int fm = 0; fm < 4; fm++)
#pragma unroll
            for (int fn = 0; fn < 4; fn++)
                mma16816(acc[fm][fn], a[fm], b[fn]);
    }

#pragma unroll
    for (int fn = 0; fn < 4; fn++) {
        int col = nbase + fn * 8 + tid4 * 2;
        float2 bb2 = *(const float2*)(b_dec + col);
#pragma unroll
        for (int fm = 0; fm < 4; fm++) {
            int row = mbase + fm * 16 + gid;
            float2 v0 = make_float2(acc[fm][fn][0] + bb2.x, acc[fm][fn][1] + bb2.y);
            float2 v1 = make_float2(acc[fm][fn][2] + bb2.x, acc[fm][fn][3] + bb2.y);
            *(float2*)(C + (size_t)row * VOC + col)       = v0;
            *(float2*)(C + (size_t)(row + 8) * VOC + col) = v1;
        }
    }
}

// ---------------- launcher ----------------
extern "C" void kernel_launch(void* const* d_in, const int* in_sizes, int n_in,
                              void* d_out, int out_size) {
    const int*   tokens = (const int*)  d_in[0];
    const float* W_ih   = (const float*)d_in[1];
    const float* W_hh   = (const float*)d_in[2];
    const float* b_ih   = (const float*)d_in[3];
    const float* b_hh   = (const float*)d_in[4];
    const float* W_dec  = (const float*)d_in[5];
    const float* b_dec  = (const float*)d_in[6];
    float* out = (float*)d_out;

    prep_kernel<<<2048, 256>>>(W_dec);
    lstm_kernel<<<NCTA, 256>>>(tokens, W_ih, W_hh, b_ih, b_hh, out + LOGN);
    dim3 g(VOC / 128, (L_SEQ * BSZ) / 128);
    gemm_kernel<<<g, 256>>>(b_dec, out);
}

// round 10
// speedup vs baseline: 2.0784x; 1.7641x over previous
#include <cuda_runtime.h>
#include <cuda_fp16.h>
#include <cstdint>
#include <cstddef>

#define L_SEQ 256
#define BSZ   16
#define VOC   32000
#define HID   512
#define NCTA  128
#define LOGN  ((size_t)L_SEQ * BSZ * VOC)

// ---------------- device scratch (allocation-free) ----------------
__device__ __half   g_wd[(size_t)VOC * HID];            // W_dec fp16   (32.8 MB)
__device__ __half   g_hs[(size_t)L_SEQ * BSZ * HID];    // hidden states fp16 (4 MB)
__device__ float    g_hbuf[2][BSZ * HID];               // double-buffered h (fp32)
__device__ unsigned g_cnt[L_SEQ];                       // grid-barrier counters

// ---------------- prep: convert W_dec to fp16, zero barrier counters ----------------
__global__ void prep_kernel(const float* __restrict__ Wd) {
    size_t n = (size_t)VOC * HID;
    size_t stride = (size_t)gridDim.x * blockDim.x;
    for (size_t i = (size_t)blockIdx.x * blockDim.x + threadIdx.x; i < n; i += stride)
        g_wd[i] = __float2half_rn(Wd[i]);
    if (blockIdx.x == 0 && threadIdx.x < L_SEQ)
        g_cnt[threadIdx.x] = 0u;
}

// ---------------- LSTM recurrence (identical to R8) ----------------
__global__ void __launch_bounds__(256, 1) lstm_kernel(
    const int*   __restrict__ tokens,
    const float* __restrict__ W_ih,
    const float* __restrict__ W_hh,
    const float* __restrict__ b_ih,
    const float* __restrict__ b_hh,
    float*       __restrict__ out_tail)   // hL then cL, each BSZ*HID
{
    __shared__ float sh[BSZ * HID];   // 32 KB staged h

    const int tid = threadIdx.x;
    const int w   = tid >> 5;
    const int l   = tid & 31;
    const int cta = blockIdx.x;
    const int p   = w & 1;
    const int bg  = w >> 1;
    const int j0  = cta * 4 + p * 2;
    const int b0  = bg * 4;

    float wreg[8][16];
#pragma unroll
    for (int r = 0; r < 8; r++) {
        const int grow = (r >> 1) * HID + j0 + (r & 1);
        const float* wp = W_hh + (size_t)grow * HID + l;
#pragma unroll
        for (int i = 0; i < 16; i++) wreg[r][i] = wp[i * 32];
    }

    const int r_o   = l >> 2;
    const int bb_o  = l & 3;
    const int row_o = (r_o >> 1) * HID + j0 + (r_o & 1);
    const float biasv = b_ih[row_o] + b_hh[row_o];

    const int jj_a = l >> 2;
    const int bb_a = l & 3;
    float cstate = 0.f;

    for (int s = 0; s < L_SEQ; s++) {
        const int tok = tokens[s * BSZ + b0 + bb_o];
        const float embb = W_ih[(size_t)row_o * VOC + tok] + biasv;

        float acc[32];
#pragma unroll
        for (int z = 0; z < 32; z++) acc[z] = 0.f;

        if (s > 0) {
            const float4* src4 = (const float4*)g_hbuf[(s - 1) & 1];
            float4* dst4 = (float4*)sh;
#pragma unroll
            for (int i = 0; i < 8; i++) dst4[tid + i * 256] = src4[tid + i * 256];
            __syncthreads();

#pragma unroll
            for (int i = 0; i < 16; i++) {
#pragma unroll
                for (int b = 0; b < 4; b++) {
                    const float hv = sh[(b0 + b) * HID + l + i * 32];
#pragma unroll
                    for (int r = 0; r < 8; r++) acc[r * 4 + b] += wreg[r][i] * hv;
                }
            }

#define RED_ROUND(D)                                                          \
            {                                                                 \
                _Pragma("unroll")                                             \
                for (int z = 0; z < (D); z++) {                               \
                    const float vk = (l & (D)) ? acc[z + (D)] : acc[z];       \
                    const float vg = (l & (D)) ? acc[z] : acc[z + (D)];       \
                    acc[z] = vk + __shfl_xor_sync(0xffffffffu, vg, (D));      \
                }                                                             \
            }
            RED_ROUND(16) RED_ROUND(8) RED_ROUND(4) RED_ROUND(2) RED_ROUND(1)
#undef RED_ROUND
        }

        const float total = acc[0] + embb;

        float gate0 = __shfl_sync(0xffffffffu, total, (l & 7));
        float gate1 = __shfl_sync(0xffffffffu, total, (l & 7) + 8);
        float gate2 = __shfl_sync(0xffffffffu, total, (l & 7) + 16);
        float gate3 = __shfl_sync(0xffffffffu, total, (l & 7) + 24);

        if (l < 8) {
            const float ii = 1.f / (1.f + __expf(-gate0));
            const float ff = 1.f / (1.f + __expf(-gate1));
            const float gg = tanhf(gate2);
            const float oo = 1.f / (1.f + __expf(-gate3));
            cstate = ff * cstate + ii * gg;
            const float h = oo * tanhf(cstate);

            const int b = b0 + bb_a, j = j0 + jj_a;
            g_hbuf[s & 1][b * HID + j] = h;
            g_hs[((size_t)s * BSZ + b) * HID + j] = __float2half_rn(h);
            if (s == L_SEQ - 1) {
                out_tail[b * HID + j] = h;
                out_tail[BSZ * HID + b * HID + j] = cstate;
            }
        }

        __syncthreads();
        if (tid == 0) {
            __threadfence();
            asm volatile("red.release.gpu.global.add.u32 [%0], %1;"
                         :: "l"(g_cnt + s), "r"(1u) : "memory");
            unsigned v;
            do {
                asm volatile("ld.acquire.gpu.u32 %0, [%1];" : "=r"(v) : "l"(g_cnt + s));
            } while (v < NCTA);
        }
        __syncthreads();
    }
}

// ================= decoder GEMM (mma.sync + cp.async smem pipeline) =================
// C[4096,32000] = A[4096,512](f16) * B[32000,512]^T(f16) + b_dec, fp32 accum.
// CTA tile 128x128, K chunked by 64, 2-stage double buffer, SW128-xor swizzle,
// ldmatrix.x4 fragment feeds, warp tile 32x64 (warps 4x2).

__device__ __forceinline__ uint32_t smem_u32(const void* p) {
    uint32_t a;
    asm("{ .reg .u64 t; cvta.to.shared.u64 t, %1; cvt.u32.u64 %0, t; }" : "=r"(a) : "l"(p));
    return a;
}
#define SWZ128(x) ((x) ^ (((x) >> 3) & 0x70))

__device__ __forceinline__ void mma16816(float* d, const uint32_t* a, const uint32_t* b) {
    asm volatile(
        "mma.sync.aligned.m16n8k16.row.col.f32.f16.f16.f32 "
        "{%0,%1,%2,%3}, {%4,%5,%6,%7}, {%8,%9}, {%0,%1,%2,%3};\n"
        : "+f"(d[0]), "+f"(d[1]), "+f"(d[2]), "+f"(d[3])
        : "r"(a[0]), "r"(a[1]), "r"(a[2]), "r"(a[3]), "r"(b[0]), "r"(b[1]));
}
__device__ __forceinline__ void ldsm_x4(uint32_t* r, uint32_t addr) {
    asm volatile("ldmatrix.sync.aligned.m8n8.x4.shared.b16 {%0,%1,%2,%3}, [%4];"
                 : "=r"(r[0]), "=r"(r[1]), "=r"(r[2]), "=r"(r[3]) : "r"(addr));
}

// smem layout (dynamic): stages at 1024; A(16K)+B(16K) per stage, 2 stages.
#define STAGE_A(s)  (1024u + ((s) & 1) * 32768u)
#define STAGE_B(s)  (STAGE_A(s) + 16384u)
#define GEMM_SMEM   66560

__device__ __forceinline__ void load_stage(uint32_t smem_base, int s, int mbase, int nbase, int tid) {
    const int kk = s * 64;
    const uint32_t ab = smem_base + STAGE_A(s);
    const uint32_t bb = smem_base + STAGE_B(s);
#pragma unroll
    for (int i = 0; i < 4; i++) {
        const int idx = tid + i * 256;
        const int row = idx >> 3;
        const int cg  = idx & 7;
        const uint32_t so = SWZ128((uint32_t)(row * 128 + cg * 16));
        const __half* ga = g_hs + (size_t)(mbase + row) * HID + kk + cg * 8;
        const __half* gb = g_wd + (size_t)(nbase + row) * HID + kk + cg * 8;
        asm volatile("cp.async.cg.shared.global [%0], [%1], 16;" :: "r"(ab + so), "l"(ga));
        asm volatile("cp.async.cg.shared.global [%0], [%1], 16;" :: "r"(bb + so), "l"(gb));
    }
    asm volatile("cp.async.commit_group;" ::: "memory");
}

__global__ void __launch_bounds__(256, 2) gemm_mma(
    const float* __restrict__ b_dec,
    float*       __restrict__ C)
{
    extern __shared__ char dsm[];
    const uint32_t smem_base = smem_u32(dsm);
    const int tid = threadIdx.x;
    const int wid = tid >> 5;
    const int lid = tid & 31;
    const int wm  = wid >> 1;           // 0..3  (M direction, 32 rows each)
    const int wn  = wid & 1;            // 0..1  (N direction, 64 cols each)
    const int nbase = blockIdx.x * 128; // N fast-varying: wave shares A in L2
    const int mbase = blockIdx.y * 128;

    // ldmatrix per-lane address components
    const int si   = lid >> 3;          // submatrix id 0..3
    const int rin  = lid & 7;           // row within submatrix
    // A: si&1 -> row+8, si>>1 -> k-half
    const int arow = wm * 32 + (si & 1) * 8 + rin;           // + fm*16
    const int akh  = (si >> 1) * 16;                         // k-half bytes
    // B: si>>1 -> n+8, si&1 -> k-half
    const int brow = wn * 64 + (si >> 1) * 8 + rin;          // + fnp*16
    const int bkh  = (si & 1) * 16;

    float acc[2][8][4];
#pragma unroll
    for (int fm = 0; fm < 2; fm++)
#pragma unroll
        for (int fn = 0; fn < 8; fn++)
#pragma unroll
            for (int z = 0; z < 4; z++) acc[fm][fn][z] = 0.f;

    load_stage(smem_base, 0, mbase, nbase, tid);
    load_stage(smem_base, 1, mbase, nbase, tid);

#pragma unroll 1
    for (int c = 0; c < 8; c++) {
        if (c < 7) asm volatile("cp.async.wait_group 1;" ::: "memory");
        else       asm volatile("cp.async.wait_group 0;" ::: "memory");
        __syncthreads();

        const uint32_t aS = smem_base + STAGE_A(c);
        const uint32_t bS = smem_base + STAGE_B(c);

#pragma unroll
        for (int kk = 0; kk < 4; kk++) {
            uint32_t a[2][4];
#pragma unroll
            for (int fm = 0; fm < 2; fm++) {
                const uint32_t byte = (uint32_t)((arow + fm * 16) * 128 + kk * 32 + akh);
                ldsm_x4(a[fm], aS + SWZ128(byte));
            }
            uint32_t b[8][2];
#pragma unroll
            for (int fnp = 0; fnp < 4; fnp++) {
                uint32_t r[4];
                const uint32_t byte = (uint32_t)((brow + fnp * 16) * 128 + kk * 32 + bkh);
                ldsm_x4(r, bS + SWZ128(byte));
                b[fnp * 2 + 0][0] = r[0]; b[fnp * 2 + 0][1] = r[1];
                b[fnp * 2 + 1][0] = r[2]; b[fnp * 2 + 1][1] = r[3];
            }
#pragma unroll
            for (int fm = 0; fm < 2; fm++)
#pragma unroll
                for (int fn = 0; fn < 8; fn++)
                    mma16816(acc[fm][fn], a[fm], b[fn]);
        }
        __syncthreads();
        if (c < 6) load_stage(smem_base, c + 2, mbase, nbase, tid);
    }

    // epilogue: direct register -> global stores with bias
    const int rrow = mbase + wm * 32 + (lid >> 2);     // + fm*16 (+8 for d2,d3)
    const int ccol = nbase + wn * 64 + (lid & 3) * 2;  // + fn*8
#pragma unroll
    for (int fn = 0; fn < 8; fn++) {
        const int col = ccol + fn * 8;
        const float2 bb2 = *(const float2*)(b_dec + col);
#pragma unroll
        for (int fm = 0; fm < 2; fm++) {
            const int row = rrow + fm * 16;
            float2 v0 = make_float2(acc[fm][fn][0] + bb2.x, acc[fm][fn][1] + bb2.y);
            float2 v1 = make_float2(acc[fm][fn][2] + bb2.x, acc[fm][fn][3] + bb2.y);
            *(float2*)(C + (size_t)row * VOC + col)       = v0;
            *(float2*)(C + (size_t)(row + 8) * VOC + col) = v1;
        }
    }
}

// ---------------- launcher ----------------
extern "C" void kernel_launch(void* const* d_in, const int* in_sizes, int n_in,
                              void* d_out, int out_size) {
    const int*   tokens = (const int*)  d_in[0];
    const float* W_ih   = (const float*)d_in[1];
    const float* W_hh   = (const float*)d_in[2];
    const float* b_ih   = (const float*)d_in[3];
    const float* b_hh   = (const float*)d_in[4];
    const float* W_dec  = (const float*)d_in[5];
    const float* b_dec  = (const float*)d_in[6];
    float* out = (float*)d_out;

    cudaFuncSetAttribute(gemm_mma, cudaFuncAttributeMaxDynamicSharedMemorySize, GEMM_SMEM);

    prep_kernel<<<2048, 256>>>(W_dec);
    lstm_kernel<<<NCTA, 256>>>(tokens, W_ih, W_hh, b_ih, b_hh, out + LOGN);
    dim3 g(VOC / 128, (L_SEQ * BSZ) / 128);
    gemm_mma<<<g, 256, GEMM_SMEM>>>(b_dec, out);
}